// round 4
// baseline (speedup 1.0000x reference)
#include <cuda_runtime.h>
#include <math.h>
#include <stdint.h>

#define BB 4096
#define EE 128
#define MMOD 8
#define NSTEPS 3
#define HDIM 256
#define CDIM 16
#define RT 16                  // rows per tile
#define NPAIR (RT/2)           // 8 row-pairs
#define NTHR 256
#define MAX_TILES (BB/RT + MMOD)   // 264

#define CHUNK_F 4096           // floats per weight chunk buffer (16KB)
#define DYN_SMEM ((4096 + 3*CHUNK_F) * 4)   // 16KB tile + 3x16KB bufs = 64KB

typedef unsigned long long ull;

// Scratch (static __device__ — no allocation allowed)
__device__ float g_X[BB * EE];                    // recurrent state, 2 MB
__device__ int   g_order[NSTEPS * BB];            // per-step rows sorted by module
__device__ int   g_tiles[NSTEPS * MAX_TILES * 3]; // (module, base, cnt) per tile

// ---------------- f32x2 helpers (FFMA2 path, sm_103a) ----------------------
__device__ __forceinline__ ull bcast2(float v) {
    ull r; asm("mov.b64 %0, {%1, %1};" : "=l"(r) : "f"(v)); return r;
}
__device__ __forceinline__ ull fma2(ull a, ull b, ull c) {
    ull d; asm("fma.rn.f32x2 %0, %1, %2, %3;" : "=l"(d) : "l"(a), "l"(b), "l"(c));
    return d;
}
__device__ __forceinline__ float2 unpack2(ull v) {
    float2 f; asm("mov.b64 {%0, %1}, %2;" : "=f"(f.x), "=f"(f.y) : "l"(v)); return f;
}
// ---------------- cp.async helpers ----------------------------------------
__device__ __forceinline__ uint32_t sptr(const void* p) {
    return (uint32_t)__cvta_generic_to_shared(p);
}
__device__ __forceinline__ void cpa16(uint32_t s, const float* g) {
    asm volatile("cp.async.ca.shared.global [%0], [%1], 16;" :: "r"(s), "l"(g));
}
__device__ __forceinline__ void cpa_commit() {
    asm volatile("cp.async.commit_group;");
}
__device__ __forceinline__ void cpa_wait1() {
    asm volatile("cp.async.wait_group 1;");
}
__device__ __forceinline__ void cpa_wait0() {
    asm volatile("cp.async.wait_group 0;");
}

// ---------------------------------------------------------------------------
// Setup: per-step counting sort of rows by module + tile metadata
// ---------------------------------------------------------------------------
__global__ void setup_kernel(const int* __restrict__ module_ids) {
    __shared__ int cnt[MMOD], cur[MMOD];
    int tid = threadIdx.x;
    for (int s = 0; s < NSTEPS; s++) {
        if (tid < MMOD) cnt[tid] = 0;
        __syncthreads();
        for (int b = tid; b < BB; b += NTHR)
            atomicAdd(&cnt[module_ids[b * NSTEPS + s]], 1);
        __syncthreads();
        if (tid == 0) {
            int o = 0, t = 0;
            for (int m = 0; m < MMOD; m++) {
                cur[m] = o;
                int c = cnt[m];
                for (int chunk = 0; chunk < c; chunk += RT) {
                    g_tiles[(s * MAX_TILES + t) * 3 + 0] = m;
                    g_tiles[(s * MAX_TILES + t) * 3 + 1] = o + chunk;
                    g_tiles[(s * MAX_TILES + t) * 3 + 2] = min(RT, c - chunk);
                    t++;
                }
                o += c;
            }
            for (; t < MAX_TILES; t++)
                g_tiles[(s * MAX_TILES + t) * 3 + 2] = 0;
        }
        __syncthreads();
        for (int b = tid; b < BB; b += NTHR) {
            int m = module_ids[b * NSTEPS + s];
            int p = atomicAdd(&cur[m], 1);
            g_order[s * BB + p] = b;
        }
        __syncthreads();
    }
}

// ---------------------------------------------------------------------------
// One recurrent step for one (module, 16-row tile). Row-PAIR packed f32x2.
// Triple-buffered cp.async weight pipeline, 1 sync per chunk.
// Dynamic SMEM floats: [0,4096) tile (X|B then H as float2), then 3x4096 bufs.
// 256 threads: o = tid&127 (output col), g = tid>>7 (0..1) -> pairs 4g..4g+3.
// Unified chunk ids: 0..7 = phase1 (Wi+Wb, 16 e-rows), 8..15 = phase2 (Wf, 32 f-rows).
// ---------------------------------------------------------------------------
__device__ __forceinline__ void step_prefetch(int gc, int buf, int tid,
                                              float* arena,
                                              const float* Wi, const float* Wb,
                                              const float* Wf) {
    uint32_t d = sptr(arena + buf * CHUNK_F);
    if (gc < 8) {
        const float* si = Wi + gc * 2048;
        const float* sb = Wb + gc * 2048;
        cpa16(d + tid * 16,        si + tid * 4);
        cpa16(d + tid * 16 + 4096, si + tid * 4 + 1024);
        cpa16(d + tid * 16 + 8192, sb + tid * 4);
        cpa16(d + tid * 16 + 12288, sb + tid * 4 + 1024);
    } else {
        const float* sf = Wf + (gc - 8) * 4096;
        cpa16(d + tid * 16,         sf + tid * 4);
        cpa16(d + tid * 16 + 4096,  sf + tid * 4 + 1024);
        cpa16(d + tid * 16 + 8192,  sf + tid * 4 + 2048);
        cpa16(d + tid * 16 + 12288, sf + tid * 4 + 3072);
    }
    cpa_commit();
}

__global__ __launch_bounds__(NTHR, 2)
void step_kernel(int s,
                 const float* __restrict__ emb,
                 const int* __restrict__ entity_ids,
                 const float* __restrict__ W_in,  const float* __restrict__ b_in,
                 const float* __restrict__ W_bias,const float* __restrict__ b_bias,
                 const float* __restrict__ W_f,   const float* __restrict__ b_f) {
    extern __shared__ float dynsm[];
    float2* SH    = (float2*)dynsm;        // 2048 float2 tile region
    float*  SHf   = dynsm;
    float*  ARENA = dynsm + 4096;          // 3 weight buffers
    __shared__ int ridx[RT], xrow[RT], eidn[RT];
    __shared__ int s_m, s_cnt;

    int tid = threadIdx.x;
    if (tid == 0) {
        int t = blockIdx.x;
        s_m   = g_tiles[(s * MAX_TILES + t) * 3 + 0];
        s_cnt = g_tiles[(s * MAX_TILES + t) * 3 + 2];
    }
    if (tid < RT) {
        int t = blockIdx.x;
        int base = g_tiles[(s * MAX_TILES + t) * 3 + 1];
        int cnt0 = g_tiles[(s * MAX_TILES + t) * 3 + 2];
        int row = (cnt0 > 0) ? g_order[s * BB + base + ((tid < cnt0) ? tid : 0)] : 0;
        ridx[tid] = row;
        xrow[tid] = (s == 0) ? entity_ids[row * (NSTEPS + 1)] : row;
        eidn[tid] = entity_ids[row * (NSTEPS + 1) + s + 1];
    }
    __syncthreads();
    const int cnt = s_cnt;
    if (cnt == 0) return;
    const int m = s_m;

    const float* Wi = W_in   + m * EE * EE;
    const float* Wb = W_bias + m * EE * EE;
    const float* Wf = W_f    + m * 2 * EE * EE;
    const float* Xsrc = (s == 0) ? emb : g_X;

    // Prime pipeline: chunks 0,1
    step_prefetch(0, 0, tid, ARENA, Wi, Wb, Wf);
    step_prefetch(1, 1, tid, ARENA, Wi, Wb, Wf);

    // Gather X tile + Bias tile into pair-interleaved SMEM
    // X: float idx p*256 + 2e + comp  (p=pair, comp=row&1), region [0,2048)
    // B: float idx 2048 + p*256 + 2e + comp, region [2048,4096)
    for (int i = tid; i < RT * EE; i += NTHR) {
        int r = i >> 7, e = i & (EE - 1);
        int p = r >> 1, comp = r & 1;
        SHf[p * 256 + 2 * e + comp]        = Xsrc[(size_t)xrow[r] * EE + e];
        SHf[2048 + p * 256 + 2 * e + comp] = emb[(size_t)eidn[r] * EE + e];
    }

    const int o  = tid & (EE - 1);
    const int g  = tid >> 7;     // 0..1
    const int p0 = g * 4;

    ull accI[4], accB[4];
#pragma unroll
    for (int p = 0; p < 4; p++) { accI[p] = 0ull; accB[p] = 0ull; }

    // ---------------- Phase 1: chunks 0..7 (16 e-rows each) ----------------
#pragma unroll
    for (int gc = 0; gc < 8; gc++) {
        cpa_wait1();             // chunk gc arrived (gc+1 may be in flight)
        __syncthreads();         // data visible + prev chunk compute done
        step_prefetch(gc + 2, (gc + 2) % 3, tid, ARENA, Wi, Wb, Wf);
        const float* WB = ARENA + (gc % 3) * CHUNK_F;
        const int e0 = gc * 16;
#pragma unroll
        for (int e = 0; e < 16; e += 2) {
            ull wi0 = bcast2(WB[(e + 0) * EE + o]);
            ull wi1 = bcast2(WB[(e + 1) * EE + o]);
            ull wb0 = bcast2(WB[2048 + (e + 0) * EE + o]);
            ull wb1 = bcast2(WB[2048 + (e + 1) * EE + o]);
            int ge = e0 + e;
#pragma unroll
            for (int p = 0; p < 4; p++) {
                int pp = p0 + p;
                ulonglong2 x2 = *(const ulonglong2*)&SH[pp * 128 + ge];
                accI[p] = fma2(x2.x, wi0, accI[p]);
                accI[p] = fma2(x2.y, wi1, accI[p]);
                ulonglong2 b2 = *(const ulonglong2*)&SH[1024 + pp * 128 + ge];
                accB[p] = fma2(b2.x, wb0, accB[p]);
                accB[p] = fma2(b2.y, wb1, accB[p]);
            }
        }
    }

    // H writeback (overwrites X|B region): H(p,f) = SH[p*256+f] as float2
    const float bi = b_in[m * EE + o];
    const float bb = b_bias[m * EE + o];
    __syncthreads();             // everyone done reading X/B
#pragma unroll
    for (int p = 0; p < 4; p++) {
        int pp = p0 + p;
        float2 vI = unpack2(accI[p]);
        float2 vB = unpack2(accB[p]);
        SH[pp * 256 + o]      = make_float2(fmaxf(vI.x + bi, 0.f), fmaxf(vI.y + bi, 0.f));
        SH[pp * 256 + EE + o] = make_float2(fmaxf(vB.x + bb, 0.f), fmaxf(vB.y + bb, 0.f));
    }

    // ---------------- Phase 2: chunks 8..15 (32 f-rows each) ---------------
    ull accF[4];
#pragma unroll
    for (int p = 0; p < 4; p++) accF[p] = 0ull;
#pragma unroll
    for (int gc = 8; gc < 16; gc++) {
        if (gc < 15) cpa_wait1(); else cpa_wait0();
        __syncthreads();         // (gc==8: also publishes H)
        if (gc + 2 < 16)
            step_prefetch(gc + 2, (gc + 2) % 3, tid, ARENA, Wi, Wb, Wf);
        const float* WB = ARENA + (gc % 3) * CHUNK_F;
        const int f0 = (gc - 8) * 32;
#pragma unroll
        for (int f = 0; f < 32; f += 2) {
            ull w0 = bcast2(WB[(f + 0) * EE + o]);
            ull w1 = bcast2(WB[(f + 1) * EE + o]);
            int gf = f0 + f;
#pragma unroll
            for (int p = 0; p < 4; p++) {
                int pp = p0 + p;
                ulonglong2 h2 = *(const ulonglong2*)&SH[pp * 256 + gf];
                accF[p] = fma2(h2.x, w0, accF[p]);
                accF[p] = fma2(h2.y, w1, accF[p]);
            }
        }
    }

    const float bf = b_f[m * EE + o];
#pragma unroll
    for (int p = 0; p < 4; p++) {
        int pp = p0 + p;
        float2 v = unpack2(accF[p]);
        int ra = 2 * pp, rb = 2 * pp + 1;
        if (ra < cnt) g_X[ridx[ra] * EE + o] = tanhf(v.x + bf);
        if (rb < cnt) g_X[ridx[rb] * EE + o] = tanhf(v.y + bf);
    }
}

// ---------------------------------------------------------------------------
// Head: out = relu(X @ W1 + b1) @ W2 + b2. 16-row tiles, 256 threads.
// Chunks 0..7 = W1 (16 e-rows x 256 = 16KB), chunk 8 = W2 (16KB).
// ---------------------------------------------------------------------------
__device__ __forceinline__ void head_prefetch(int gc, int buf, int tid,
                                              float* arena,
                                              const float* W1, const float* W2) {
    uint32_t d = sptr(arena + buf * CHUNK_F);
    const float* src = (gc < 8) ? (W1 + gc * 4096) : W2;
    cpa16(d + tid * 16,         src + tid * 4);
    cpa16(d + tid * 16 + 4096,  src + tid * 4 + 1024);
    cpa16(d + tid * 16 + 8192,  src + tid * 4 + 2048);
    cpa16(d + tid * 16 + 12288, src + tid * 4 + 3072);
    cpa_commit();
}

__global__ __launch_bounds__(NTHR, 2)
void head_kernel(const float* __restrict__ W1, const float* __restrict__ b1,
                 const float* __restrict__ W2, const float* __restrict__ b2,
                 float* __restrict__ out) {
    extern __shared__ float dynsm[];
    float2* SH    = (float2*)dynsm;        // X: (p,e)=SH[p*128+e]; H: (p,h)=SH[p*256+h]
    float*  SHf   = dynsm;
    float*  ARENA = dynsm + 4096;
    int tid  = threadIdx.x;
    int row0 = blockIdx.x * RT;

    head_prefetch(0, 0, tid, ARENA, W1, W2);
    head_prefetch(1, 1, tid, ARENA, W1, W2);

    for (int i = tid; i < RT * EE; i += NTHR) {
        int r = i >> 7, e = i & (EE - 1);
        int p = r >> 1, comp = r & 1;
        SHf[p * 256 + 2 * e + comp] = g_X[(row0 + r) * EE + e];
    }

    const int oh = tid;  // 0..255
    ull acc[8];
#pragma unroll
    for (int p = 0; p < 8; p++) acc[p] = 0ull;

#pragma unroll
    for (int gc = 0; gc < 8; gc++) {
        cpa_wait1();
        __syncthreads();
        if (gc + 2 <= 8)
            head_prefetch(gc + 2, (gc + 2) % 3, tid, ARENA, W1, W2);
        const float* WB = ARENA + (gc % 3) * CHUNK_F;
        const int e0 = gc * 16;
#pragma unroll
        for (int e = 0; e < 16; e += 2) {
            ull w0 = bcast2(WB[(e + 0) * HDIM + oh]);
            ull w1 = bcast2(WB[(e + 1) * HDIM + oh]);
            int ge = e0 + e;
#pragma unroll
            for (int p = 0; p < 8; p++) {
                ulonglong2 x2 = *(const ulonglong2*)&SH[p * 128 + ge];
                acc[p] = fma2(x2.x, w0, acc[p]);
                acc[p] = fma2(x2.y, w1, acc[p]);
            }
        }
    }

    const float bh = b1[oh];
    __syncthreads();   // all X reads done before H overwrite
#pragma unroll
    for (int p = 0; p < 8; p++) {
        float2 v = unpack2(acc[p]);
        SH[p * 256 + oh] = make_float2(fmaxf(v.x + bh, 0.f), fmaxf(v.y + bh, 0.f));
    }
    cpa_wait0();       // W2 chunk (gc=8) arrived
    __syncthreads();   // publish H

    // gemm2: each thread one (row, c); W2 in buffer 8%3=2
    const float* WB2 = ARENA + 2 * CHUNK_F;
    const int row = tid >> 4;          // 0..15
    const int c   = tid & (CDIM - 1);
    const int pr  = row >> 1, comp = row & 1;
    float sum = b2[c];
#pragma unroll 4
    for (int h = 0; h < HDIM; h += 2) {
        float2 h0 = SH[pr * 256 + h];
        float2 h1 = SH[pr * 256 + h + 1];
        float v0 = comp ? h0.y : h0.x;
        float v1 = comp ? h1.y : h1.x;
        sum = fmaf(v0, WB2[(h + 0) * CDIM + c], sum);
        sum = fmaf(v1, WB2[(h + 1) * CDIM + c], sum);
    }
    out[(row0 + row) * CDIM + c] = sum;
}

// ---------------------------------------------------------------------------
extern "C" void kernel_launch(void* const* d_in, const int* in_sizes, int n_in,
                              void* d_out, int out_size) {
    const int*   entity_ids = (const int*)d_in[0];
    const int*   module_ids = (const int*)d_in[1];
    const float* emb        = (const float*)d_in[2];
    const float* W_in       = (const float*)d_in[3];
    const float* b_in       = (const float*)d_in[4];
    const float* W_bias     = (const float*)d_in[5];
    const float* b_bias     = (const float*)d_in[6];
    const float* W_f        = (const float*)d_in[7];
    const float* b_f        = (const float*)d_in[8];
    const float* W1         = (const float*)d_in[9];
    const float* b1         = (const float*)d_in[10];
    const float* W2         = (const float*)d_in[11];
    const float* b2         = (const float*)d_in[12];
    float* out = (float*)d_out;

    cudaFuncSetAttribute(step_kernel, cudaFuncAttributeMaxDynamicSharedMemorySize, DYN_SMEM);
    cudaFuncSetAttribute(head_kernel, cudaFuncAttributeMaxDynamicSharedMemorySize, DYN_SMEM);

    setup_kernel<<<1, NTHR>>>(module_ids);
    for (int s = 0; s < NSTEPS; s++)
        step_kernel<<<MAX_TILES, NTHR, DYN_SMEM>>>(s, emb, entity_ids,
                                                   W_in, b_in, W_bias, b_bias, W_f, b_f);
    head_kernel<<<BB / RT, NTHR, DYN_SMEM>>>(W1, b1, W2, b2, out);
}